// round 4
// baseline (speedup 1.0000x reference)
#include <cuda_runtime.h>

#define BB 16
#define CC 128
#define NN 1024
#define KK 9

// ---- scratch (device globals; no allocation allowed) ----
__device__ float  g_sq[BB*NN];
__device__ float  g_u[BB*NN*CC];     // u = f@W1[:C] + b1
__device__ float  g_v[BB*NN*CC];     // v = f@W1[C:]
__device__ int    g_idx[BB*NN*KK];   // GLOBAL point indices (b*NN + m)
__device__ float  g_pre[BB*NN*CC];   // pre-BN output, (b,n,c)
__device__ double g_dsum[CC];
__device__ double g_dsqs[CC];
__device__ float  g_scale[CC];
__device__ float  g_shift[CC];

// ---------------- K0: zero BN accumulators ----------------
__global__ void k_init() {
    int t = threadIdx.x;
    g_dsum[t] = 0.0;
    g_dsqs[t] = 0.0;
}

// ---------------- K1: per-point sq, u, v ----------------
// block = 128 threads, handles 16 consecutive points (same b since 1024%16==0)
__global__ void __launch_bounds__(128) k_point(
    const float* __restrict__ x, const float* __restrict__ W1,
    const float* __restrict__ b1)
{
    __shared__ float fs[16*130];   // stride 130: conflict-free stores
    int t = threadIdx.x;
    int base = blockIdx.x * 16;
    int b = base / NN, n0 = base % NN;

    // load 16 points x 128 channels (coalesced over n)
    {
        int p = t & 15, c0 = t >> 4;   // c0 in 0..7
        #pragma unroll
        for (int i = 0; i < 16; i++) {
            int c = c0 + i*8;
            fs[p*130 + c] = x[(b*CC + c)*NN + n0 + p];
        }
    }
    __syncthreads();

    if (t < 16) {
        float s = 0.f;
        #pragma unroll 4
        for (int c = 0; c < CC; c++) { float f = fs[t*130+c]; s += f*f; }
        g_sq[base + t] = s;
    }

    int j = t;
    float accU[16], accV[16];
    #pragma unroll
    for (int p = 0; p < 16; p++) { accU[p]=0.f; accV[p]=0.f; }
    for (int c = 0; c < CC; c++) {
        float wa = W1[c*CC + j];
        float wb = W1[(CC+c)*CC + j];
        #pragma unroll
        for (int p = 0; p < 16; p++) {
            float f = fs[p*130 + c];
            accU[p] = fmaf(f, wa, accU[p]);
            accV[p] = fmaf(f, wb, accV[p]);
        }
    }
    float bj = b1[j];
    #pragma unroll
    for (int p = 0; p < 16; p++) {
        g_u[(base+p)*CC + j] = accU[p] + bj;
        g_v[(base+p)*CC + j] = accV[p];
    }
}

// ---------------- K2: exact KNN (top-9 smallest d2) ----------------
// block = (n-tile of 128, b); thread owns one query row in registers.
// m-tiles of 64 staged in smem as [c][m] so vec4 reads over m broadcast.
__global__ void __launch_bounds__(128) k_knn(const float* __restrict__ x)
{
    __shared__ float Am[CC*64];   // [c][m]
    __shared__ float sqs[64];
    int t = threadIdx.x;
    int b = blockIdx.y;
    int n = blockIdx.x * 128 + t;

    float rf[CC];
    #pragma unroll
    for (int c = 0; c < CC; c++) rf[c] = x[(b*CC + c)*NN + n];
    float sq_n = g_sq[b*NN + n];

    float bd[KK]; int bi[KK];
    #pragma unroll
    for (int k = 0; k < KK; k++) { bd[k] = 3.4e38f; bi[k] = 0; }
    float wmax = 3.4e38f; int wpos = 0;

    for (int mt = 0; mt < NN/64; mt++) {
        int mb = mt*64;
        __syncthreads();
        for (int i = t; i < CC*64; i += 128) {
            int c = i >> 6, m = i & 63;
            Am[c*64 + m] = x[(b*CC + c)*NN + mb + m];   // coalesced ld, conflict-free st
        }
        if (t < 64) sqs[t] = g_sq[b*NN + mb + t];
        __syncthreads();

        for (int mg = 0; mg < 64; mg += 4) {
            float d0=0.f, d1=0.f, d2a=0.f, d3=0.f;
            #pragma unroll
            for (int c = 0; c < CC; c++) {
                float4 am = *(const float4*)&Am[c*64 + mg];   // broadcast
                d0 = fmaf(rf[c], am.x, d0);
                d1 = fmaf(rf[c], am.y, d1);
                d2a= fmaf(rf[c], am.z, d2a);
                d3 = fmaf(rf[c], am.w, d3);
            }
            float dots[4] = {d0, d1, d2a, d3};
            #pragma unroll
            for (int q = 0; q < 4; q++) {
                int m = mb + mg + q;
                float d2v = sq_n + sqs[mg+q] - 2.f*dots[q];
                if (d2v < wmax) {
                    #pragma unroll
                    for (int k = 0; k < KK; k++)
                        if (k == wpos) { bd[k] = d2v; bi[k] = m; }
                    wmax = bd[0]; wpos = 0;
                    #pragma unroll
                    for (int k = 1; k < KK; k++)
                        if (bd[k] > wmax) { wmax = bd[k]; wpos = k; }
                }
            }
        }
    }
    // store GLOBAL point index so downstream gathers stay in batch b
    #pragma unroll
    for (int k = 0; k < KK; k++) g_idx[(b*NN + n)*KK + k] = b*NN + bi[k];
}

// ---------------- K3: gather + leaky + (h @ W2) + max_k + BN stats ----------------
// block = 128 threads, 16 points. Thread j keeps W2[:,j] column in registers.
__global__ void __launch_bounds__(128, 3) k_edge(
    const float* __restrict__ W2, const float* __restrict__ b2)
{
    __shared__ __align__(16) float h1s[KK*CC];
    int j = threadIdx.x;
    int base = blockIdx.x * 16;

    float wcol[CC];
    #pragma unroll
    for (int c = 0; c < CC; c++) wcol[c] = W2[c*CC + j];   // coalesced across j
    float b2j = b2[j];

    float sumL = 0.f, sqL = 0.f;
    for (int p = 0; p < 16; p++) {
        int pt = base + p;
        __syncthreads();   // protect h1s reuse
        float uj = g_u[pt*CC + j];
        float vj = g_v[pt*CC + j];
        float base_h = uj - vj;
        #pragma unroll
        for (int k = 0; k < KK; k++) {
            int nb = g_idx[pt*KK + k];            // uniform -> broadcast (global idx)
            float h = base_h + g_v[nb*CC + j];    // coalesced gather
            h1s[k*CC + j] = (h >= 0.f) ? h : 0.2f*h;
        }
        __syncthreads();

        float acc[KK];
        #pragma unroll
        for (int k = 0; k < KK; k++) acc[k] = 0.f;
        #pragma unroll
        for (int c = 0; c < CC; c += 4) {
            #pragma unroll
            for (int k = 0; k < KK; k++) {
                float4 h4 = *(const float4*)&h1s[k*CC + c];  // broadcast
                float a = acc[k];
                a = fmaf(h4.x, wcol[c  ], a);
                a = fmaf(h4.y, wcol[c+1], a);
                a = fmaf(h4.z, wcol[c+2], a);
                a = fmaf(h4.w, wcol[c+3], a);
                acc[k] = a;
            }
        }
        float m = acc[0];
        #pragma unroll
        for (int k = 1; k < KK; k++) m = fmaxf(m, acc[k]);
        float pre = m + b2j;
        g_pre[pt*CC + j] = pre;
        sumL += pre; sqL += pre*pre;
    }
    atomicAdd(&g_dsum[j], (double)sumL);
    atomicAdd(&g_dsqs[j], (double)sqL);
}

// ---------------- K4: BN scale/shift ----------------
__global__ void k_bn(const float* __restrict__ gamma, const float* __restrict__ beta)
{
    int j = threadIdx.x;
    const double inv = 1.0 / (double)(BB*NN);
    double mean = g_dsum[j] * inv;
    double var  = g_dsqs[j] * inv - mean*mean;
    float sc = gamma[j] * rsqrtf((float)var + 1e-5f);
    g_scale[j] = sc;
    g_shift[j] = beta[j] - (float)mean * sc;
}

// ---------------- K5: transpose + BN apply + residual + ReLU ----------------
__global__ void __launch_bounds__(256) k_apply(
    const float* __restrict__ x, float* __restrict__ out)
{
    __shared__ float tile[32][33];
    int b  = blockIdx.z;
    int c0 = blockIdx.y * 32;
    int n0 = blockIdx.x * 32;
    int t = threadIdx.x;
    int cj = t & 31, i0 = t >> 5;

    for (int i = i0; i < 32; i += 8)
        tile[i][cj] = g_pre[((b*NN) + n0 + i)*CC + c0 + cj];   // coalesced over c
    __syncthreads();

    int nj = t & 31;
    for (int ci = i0; ci < 32; ci += 8) {
        int c = c0 + ci;
        int o = (b*CC + c)*NN + n0 + nj;
        float v = tile[nj][ci] * g_scale[c] + g_shift[c] + x[o];
        out[o] = v > 0.f ? v : 0.f;   // coalesced over n
    }
}

// ---------------- launch ----------------
extern "C" void kernel_launch(void* const* d_in, const int* in_sizes, int n_in,
                              void* d_out, int out_size)
{
    const float* x     = (const float*)d_in[0];
    const float* W1    = (const float*)d_in[1];
    const float* b1    = (const float*)d_in[2];
    const float* W2    = (const float*)d_in[3];
    const float* b2    = (const float*)d_in[4];
    const float* gamma = (const float*)d_in[5];
    const float* beta  = (const float*)d_in[6];
    float* out = (float*)d_out;

    k_init <<<1, 128>>>();
    k_point<<<BB*NN/16, 128>>>(x, W1, b1);
    k_knn  <<<dim3(NN/128, BB), 128>>>(x);
    k_edge <<<BB*NN/16, 128>>>(W2, b2);
    k_bn   <<<1, 128>>>(gamma, beta);
    k_apply<<<dim3(NN/32, CC/32, BB), 256>>>(x, out);
}